// round 2
// baseline (speedup 1.0000x reference)
#include <cuda_runtime.h>
#include <math.h>

#define Bn 512
#define Tn 200
#define PARTY 2
#define D_M 1024
#define D_G 512
#define D_P 512
#define D_E 512

// Output layout (flattened tuple): g_, q_, e_, c_, alpha_out
#define G_OFF 0
#define Q_OFF (Bn * D_G)                    // 262144
#define E_OFF (Q_OFF + Bn * PARTY * D_P)    // 786432
#define C_OFF (E_OFF + Bn * PARTY * D_E)    // 1310720
#define A_OFF (C_OFF + Bn * D_G)            // 1572864

// ---------------- static scratch (no allocations allowed) ----------------
__device__ float d_scale_buf[Tn * Bn];
__device__ float d_m_buf[Bn];
__device__ float d_s_buf[Bn];
__device__ float d_xcat_buf[(Bn * PARTY) * (D_M + D_G)];
__device__ float d_gi_buf[(Bn * PARTY) * 3 * D_G];
__device__ float d_gh_buf[(Bn * PARTY) * 3 * D_G];
__device__ float d_xt_buf[Bn * PARTY * D_P];
__device__ float d_Qacc_buf[Bn * PARTY * D_P];
__device__ float d_e0sw_buf[Bn * PARTY * D_E];

// ---------------- block reduction (256 threads, 8 warps) ----------------
__device__ __forceinline__ float block_reduce_sum(float val, float* sbuf) {
    int tid = threadIdx.x;
    int lane = tid & 31;
    int wid = tid >> 5;
    #pragma unroll
    for (int o = 16; o > 0; o >>= 1) val += __shfl_down_sync(0xffffffffu, val, o);
    if (lane == 0) sbuf[wid] = val;
    __syncthreads();
    if (wid == 0) {
        float v = (lane < 8) ? sbuf[lane] : 0.0f;
        #pragma unroll
        for (int o = 4; o > 0; o >>= 1) v += __shfl_down_sync(0xffffffffu, v, o);
        if (lane == 0) sbuf[0] = v;
    }
    __syncthreads();
    float r = sbuf[0];
    __syncthreads();   // protect sbuf reuse next iteration
    return r;
}

// ---------------- attention over g_hist (online softmax, single pass) ----------------
// one block per b; 256 threads, each owns 2 columns (float2)
__global__ __launch_bounds__(256) void attn_g_kernel(
    const float* __restrict__ g_hist, const float* __restrict__ w_att,
    float* __restrict__ scale_out, float* __restrict__ m_out, float* __restrict__ s_out,
    float* __restrict__ c_out)
{
    __shared__ float sbuf[32];
    int b = blockIdx.x;
    int tid = threadIdx.x;
    const size_t tstride = (size_t)Bn * D_G;
    const float* base = g_hist + (size_t)b * D_G + 2 * tid;
    float2 wa = *(const float2*)(w_att + 2 * tid);

    float m = -INFINITY, s = 0.0f;
    float2 acc = make_float2(0.0f, 0.0f);
    float2 v = *(const float2*)base;
    for (int t = 0; t < Tn; t++) {
        float2 vn = make_float2(0.0f, 0.0f);
        if (t + 1 < Tn) vn = *(const float2*)(base + (size_t)(t + 1) * tstride);
        float part = v.x * wa.x + v.y * wa.y;
        float sc = block_reduce_sum(part, sbuf);
        if (tid == 0) scale_out[t * Bn + b] = sc;
        float nm = fmaxf(m, sc);
        float rs = __expf(m - nm);
        float cf = __expf(sc - nm);
        acc.x = acc.x * rs + cf * v.x;
        acc.y = acc.y * rs + cf * v.y;
        s = s * rs + cf;
        m = nm;
        v = vn;
    }
    float inv = 1.0f / s;
    float2 o = make_float2(acc.x * inv, acc.y * inv);
    *(float2*)(c_out + (size_t)b * D_G + 2 * tid) = o;
    if (tid == 0) { m_out[b] = m; s_out[b] = s; }
}

// alpha_out[b, 0, t] = exp(scale[t,b] - m[b]) / s[b]
__global__ void alpha_kernel(const float* __restrict__ scale_in,
                             const float* __restrict__ m_in, const float* __restrict__ s_in,
                             float* __restrict__ aout)
{
    int i = blockIdx.x * blockDim.x + threadIdx.x;
    if (i >= Tn * Bn) return;
    int t = i / Bn;
    int b = i - t * Bn;
    aout[b * Tn + t] = __expf(scale_in[i] - m_in[b]) / s_in[b];
}

// ---------------- attention over q_hist (online softmax, single pass) ----------------
// one block per n = b*2 + p
__global__ __launch_bounds__(256) void attn_q_kernel(
    const float* __restrict__ q_hist, const float* __restrict__ xt,
    float* __restrict__ Qout)
{
    __shared__ float sbuf[32];
    int n = blockIdx.x;
    int tid = threadIdx.x;
    const size_t tstride = (size_t)Bn * PARTY * D_P;
    const float* base = q_hist + (size_t)n * D_P + 2 * tid;
    float2 x2 = *(const float2*)(xt + (size_t)n * D_P + 2 * tid);

    float m = -INFINITY, s = 0.0f;
    float2 acc = make_float2(0.0f, 0.0f);
    float2 v = *(const float2*)base;
    for (int t = 0; t < Tn; t++) {
        float2 vn = make_float2(0.0f, 0.0f);
        if (t + 1 < Tn) vn = *(const float2*)(base + (size_t)(t + 1) * tstride);
        float part = v.x * x2.x + v.y * x2.y;
        float sc = block_reduce_sum(part, sbuf);
        float nm = fmaxf(m, sc);
        float rs = __expf(m - nm);
        float cf = __expf(sc - nm);
        acc.x = acc.x * rs + cf * v.x;
        acc.y = acc.y * rs + cf * v.y;
        s = s * rs + cf;
        m = nm;
        v = vn;
    }
    float inv = 1.0f / s;
    float2 o = make_float2(acc.x * inv, acc.y * inv);
    *(float2*)(Qout + (size_t)n * D_P + 2 * tid) = o;
}

// ---------------- SGEMM: C[n,m] = A[n,k] * W[m,k]^T + bias[m] ----------------
// 128x128 tile, TK=8, 256 threads, 8x8 microtile using packed f32x2 FMA.
// grid: (M/128, N/128)
__global__ __launch_bounds__(256) void sgemm_nt(
    const float* __restrict__ A, const float* __restrict__ W,
    const float* __restrict__ bias, float* __restrict__ C,
    int K, int M)
{
    __shared__ float As[2][8][128];
    __shared__ float Ws[2][8][128];
    int n0 = blockIdx.y * 128;
    int m0 = blockIdx.x * 128;
    int tid = threadIdx.x;
    int lrow = tid >> 1;          // 0..127
    int lk = (tid & 1) * 4;       // 0 or 4
    int tx = tid & 15;            // 0..15 -> 8 output cols
    int ty = tid >> 4;            // 0..15 -> 8 output rows

    const float* Ap = A + (size_t)(n0 + lrow) * K + lk;
    const float* Wp = W + (size_t)(m0 + lrow) * K + lk;

    unsigned long long acc[8][4];
    #pragma unroll
    for (int i = 0; i < 8; i++)
        #pragma unroll
        for (int j = 0; j < 4; j++) acc[i][j] = 0ull;

    float4 a4 = *(const float4*)Ap;
    float4 w4 = *(const float4*)Wp;
    int buf = 0;
    for (int k0 = 0; k0 < K; k0 += 8) {
        As[buf][lk + 0][lrow] = a4.x; As[buf][lk + 1][lrow] = a4.y;
        As[buf][lk + 2][lrow] = a4.z; As[buf][lk + 3][lrow] = a4.w;
        Ws[buf][lk + 0][lrow] = w4.x; Ws[buf][lk + 1][lrow] = w4.y;
        Ws[buf][lk + 2][lrow] = w4.z; Ws[buf][lk + 3][lrow] = w4.w;
        __syncthreads();
        if (k0 + 8 < K) {
            a4 = *(const float4*)(Ap + k0 + 8);
            w4 = *(const float4*)(Wp + k0 + 8);
        }
        #pragma unroll
        for (int k = 0; k < 8; k++) {
            float4 av0 = *(const float4*)&As[buf][k][ty * 8];
            float4 av1 = *(const float4*)&As[buf][k][ty * 8 + 4];
            const unsigned long long* wp2 = (const unsigned long long*)&Ws[buf][k][tx * 8];
            unsigned long long w2[4];
            w2[0] = wp2[0]; w2[1] = wp2[1]; w2[2] = wp2[2]; w2[3] = wp2[3];
            float ar[8] = {av0.x, av0.y, av0.z, av0.w, av1.x, av1.y, av1.z, av1.w};
            #pragma unroll
            for (int i = 0; i < 8; i++) {
                unsigned int ai = __float_as_uint(ar[i]);
                unsigned long long a2;
                asm("mov.b64 %0, {%1, %1};" : "=l"(a2) : "r"(ai));
                #pragma unroll
                for (int j = 0; j < 4; j++) {
                    asm("fma.rn.f32x2 %0, %1, %2, %0;"
                        : "+l"(acc[i][j]) : "l"(a2), "l"(w2[j]));
                }
            }
        }
        buf ^= 1;
    }

    #pragma unroll
    for (int i = 0; i < 8; i++) {
        int row = n0 + ty * 8 + i;
        float* cp = C + (size_t)row * M + m0 + tx * 8;
        #pragma unroll
        for (int j = 0; j < 4; j++) {
            unsigned int lo_u, hi_u;
            asm("mov.b64 {%0, %1}, %2;" : "=r"(lo_u), "=r"(hi_u) : "l"(acc[i][j]));
            float lo = __uint_as_float(lo_u);
            float hi = __uint_as_float(hi_u);
            int col = m0 + tx * 8 + 2 * j;
            if (bias) { lo += bias[col]; hi += bias[col + 1]; }
            float2 o = make_float2(lo, hi);
            *(float2*)(cp + 2 * j) = o;
        }
    }
}

// ---------------- GRU gating epilogue ----------------
// mode 0: plain. mode 1: party mix (h == q0; qmask flattened [B*PARTY])
__global__ void gru_epi(const float* __restrict__ gi, const float* __restrict__ gh,
                        const float* __restrict__ h, float* __restrict__ out,
                        int N, int D, int mode, const float* __restrict__ qmask)
{
    int idx = blockIdx.x * blockDim.x + threadIdx.x;
    if (idx >= N * D) return;
    int n = idx / D;
    int j = idx - n * D;
    size_t base = (size_t)n * 3 * D + j;
    float ir = gi[base],        hr = gh[base];
    float iz = gi[base + D],    hz = gh[base + D];
    float in_ = gi[base + 2 * D], hn = gh[base + 2 * D];
    float r = 1.0f / (1.0f + __expf(-(ir + hr)));
    float z = 1.0f / (1.0f + __expf(-(iz + hz)));
    float nn = tanhf(in_ + r * hn);
    float hv = h[idx];
    float val = (1.0f - z) * nn + z * hv;
    if (mode == 1) {
        float qm = qmask[n];
        val = hv * (1.0f - qm) + val * qm;
    }
    out[idx] = val;
}

// ---------------- small builders ----------------
__global__ void build_xcat_g(const float* __restrict__ U, const float* __restrict__ qmask,
                             const float* __restrict__ q0, float* __restrict__ xcat)
{
    int idx = blockIdx.x * blockDim.x + threadIdx.x;
    const int W = D_M + D_P;
    if (idx >= Bn * W) return;
    int b = idx / W;
    int c = idx - b * W;
    float v;
    if (c < D_M) {
        v = U[(size_t)b * D_M + c];
    } else {
        int qi = (qmask[b * 2 + 1] > qmask[b * 2 + 0]) ? 1 : 0;
        v = q0[(size_t)(b * 2 + qi) * D_P + (c - D_M)];
    }
    xcat[idx] = v;
}

__global__ void build_xcat_p(const float* __restrict__ U, const float* __restrict__ c_,
                             float* __restrict__ xcat)
{
    int idx = blockIdx.x * blockDim.x + threadIdx.x;
    const int W = D_M + D_G;
    if (idx >= Bn * PARTY * W) return;
    int n = idx / W;
    int c = idx - n * W;
    int b = n >> 1;
    float v;
    if (c < D_M) v = U[(size_t)b * D_M + c];
    else         v = c_[(size_t)b * D_G + (c - D_M)];
    xcat[idx] = v;
}

__global__ void build_e0sw(const float* __restrict__ e0, float* __restrict__ e0sw)
{
    int idx = blockIdx.x * blockDim.x + threadIdx.x;
    if (idx >= Bn * PARTY * D_E) return;
    int n = idx / D_E;
    int j = idx - n * D_E;
    int b = n >> 1;
    int p = n & 1;
    e0sw[idx] = e0[(size_t)(b * 2 + (1 - p)) * D_E + j];
}

// ---------------- launch ----------------
extern "C" void kernel_launch(void* const* d_in, const int* in_sizes, int n_in,
                              void* d_out, int out_size)
{
    const float* U       = (const float*)d_in[0];
    const float* qmask   = (const float*)d_in[1];
    const float* g_hist  = (const float*)d_in[2];
    const float* q0      = (const float*)d_in[3];
    const float* q_hist  = (const float*)d_in[4];
    const float* e0      = (const float*)d_in[5];
    const float* w_ih_g  = (const float*)d_in[6];
    const float* w_hh_g  = (const float*)d_in[7];
    const float* b_ih_g  = (const float*)d_in[8];
    const float* b_hh_g  = (const float*)d_in[9];
    const float* w_ih_p  = (const float*)d_in[10];
    const float* w_hh_p  = (const float*)d_in[11];
    const float* b_ih_p  = (const float*)d_in[12];
    const float* b_hh_p  = (const float*)d_in[13];
    const float* w_ih_e  = (const float*)d_in[14];
    const float* w_hh_e  = (const float*)d_in[15];
    const float* b_ih_e  = (const float*)d_in[16];
    const float* b_hh_e  = (const float*)d_in[17];
    const float* w_att   = (const float*)d_in[18];
    const float* w_trans = (const float*)d_in[19];
    float* out = (float*)d_out;

    float *scale_p, *m_p, *s_p, *xcat_p, *gi_p, *gh_p, *xt_p, *Q_p, *e0sw_p;
    cudaGetSymbolAddress((void**)&scale_p, d_scale_buf);
    cudaGetSymbolAddress((void**)&m_p,     d_m_buf);
    cudaGetSymbolAddress((void**)&s_p,     d_s_buf);
    cudaGetSymbolAddress((void**)&xcat_p,  d_xcat_buf);
    cudaGetSymbolAddress((void**)&gi_p,    d_gi_buf);
    cudaGetSymbolAddress((void**)&gh_p,    d_gh_buf);
    cudaGetSymbolAddress((void**)&xt_p,    d_xt_buf);
    cudaGetSymbolAddress((void**)&Q_p,     d_Qacc_buf);
    cudaGetSymbolAddress((void**)&e0sw_p,  d_e0sw_buf);

    const float* g_last = g_hist + (size_t)(Tn - 1) * Bn * D_G;

    // 1) g-attention: scale logits + m/s + c_ (single pass, online softmax)
    attn_g_kernel<<<Bn, 256>>>(g_hist, w_att, scale_p, m_p, s_p, out + C_OFF);
    // 2) alpha output
    alpha_kernel<<<(Tn * Bn + 255) / 256, 256>>>(scale_p, m_p, s_p, out + A_OFF);

    // 3) GRU g
    build_xcat_g<<<(Bn * (D_M + D_P) + 255) / 256, 256>>>(U, qmask, q0, xcat_p);
    sgemm_nt<<<dim3((3 * D_G) / 128, Bn / 128), 256>>>(xcat_p, w_ih_g, b_ih_g, gi_p, D_M + D_P, 3 * D_G);
    sgemm_nt<<<dim3((3 * D_G) / 128, Bn / 128), 256>>>(g_last, w_hh_g, b_hh_g, gh_p, D_G, 3 * D_G);
    gru_epi<<<(Bn * D_G + 255) / 256, 256>>>(gi_p, gh_p, g_last, out + G_OFF, Bn, D_G, 0, nullptr);

    // 4) GRU p (depends on c_)
    build_xcat_p<<<(Bn * PARTY * (D_M + D_G) + 255) / 256, 256>>>(U, out + C_OFF, xcat_p);
    sgemm_nt<<<dim3((3 * D_P) / 128, (Bn * PARTY) / 128), 256>>>(xcat_p, w_ih_p, b_ih_p, gi_p, D_M + D_G, 3 * D_P);
    sgemm_nt<<<dim3((3 * D_P) / 128, (Bn * PARTY) / 128), 256>>>(q0, w_hh_p, b_hh_p, gh_p, D_P, 3 * D_P);
    gru_epi<<<(Bn * PARTY * D_P + 255) / 256, 256>>>(gi_p, gh_p, q0, out + Q_OFF, Bn * PARTY, D_P, 1, qmask);

    // 5) q-attention: xt = e0_swapped @ w_trans^T, then online softmax over q_hist
    build_e0sw<<<(Bn * PARTY * D_E + 255) / 256, 256>>>(e0, e0sw_p);
    sgemm_nt<<<dim3(D_P / 128, (Bn * PARTY) / 128), 256>>>(e0sw_p, w_trans, nullptr, xt_p, D_E, D_P);
    attn_q_kernel<<<Bn * PARTY, 256>>>(q_hist, xt_p, Q_p);

    // 6) GRU e
    sgemm_nt<<<dim3((3 * D_E) / 128, (Bn * PARTY) / 128), 256>>>(Q_p, w_ih_e, b_ih_e, gi_p, D_P, 3 * D_E);
    sgemm_nt<<<dim3((3 * D_E) / 128, (Bn * PARTY) / 128), 256>>>(e0, w_hh_e, b_hh_e, gh_p, D_E, 3 * D_E);
    gru_epi<<<(Bn * PARTY * D_E + 255) / 256, 256>>>(gi_p, gh_p, e0, out + E_OFF, Bn * PARTY, D_E, 0, nullptr);
}

// round 4
// speedup vs baseline: 1.8481x; 1.8481x over previous
#include <cuda_runtime.h>
#include <math.h>

#define Bn 512
#define Tn 200
#define PARTY 2
#define D_M 1024
#define D_G 512
#define D_P 512
#define D_E 512

// Output layout (flattened tuple): g_, q_, e_, c_, alpha_out
#define G_OFF 0
#define Q_OFF (Bn * D_G)                    // 262144
#define E_OFF (Q_OFF + Bn * PARTY * D_P)    // 786432
#define C_OFF (E_OFF + Bn * PARTY * D_E)    // 1310720
#define A_OFF (C_OFF + Bn * D_G)            // 1572864

// ---------------- static scratch (no allocations allowed) ----------------
__device__ float d_scale_buf[Tn * Bn];
__device__ float d_m_buf[Bn];
__device__ float d_s_buf[Bn];
__device__ float d_xcat_buf[(Bn * PARTY) * (D_M + D_G)];
__device__ float d_gi_buf[(Bn * PARTY) * 3 * D_G];
__device__ float d_gh_buf[(Bn * PARTY) * 3 * D_G];
__device__ float d_ghp_buf[(Bn * PARTY) * 3 * D_P];  // dedicated: p-GRU hidden gemm
__device__ float d_xt_buf[Bn * PARTY * D_P];
__device__ float d_Qacc_buf[Bn * PARTY * D_P];
__device__ float d_e0sw_buf[Bn * PARTY * D_E];
__device__ float d_gih_buf[Bn * 3 * D_P];   // dedup gi_p (N=512)

// =====================================================================
// Attention: per-warp online softmax, no per-timestep block syncs.
// Block = one (b) [or (b,p)] row. 8 warps; warp w owns t = w + 8*i.
// Lane l owns 16 cols: l*4 + j*128 + u  (4x float4, fully coalesced).
// =====================================================================
template<int WRITE_SCALE>
__device__ __forceinline__ void attn_body(
    const float* __restrict__ hist, size_t tstride, size_t row_off,
    const float* __restrict__ wvec,         // 512-dim query vector (global)
    float* __restrict__ scale_out, int b,   // only if WRITE_SCALE
    float* __restrict__ m_out, float* __restrict__ s_out,
    float* __restrict__ c_out)
{
    __shared__ float s_m[8], s_s[8], s_w8[8];
    __shared__ float s_acc[8][512];

    int tid = threadIdx.x;
    int lane = tid & 31;
    int w = tid >> 5;

    const float* base = hist + row_off + (size_t)lane * 4;
    // query vector into regs
    float q[16];
    #pragma unroll
    for (int j = 0; j < 4; j++) {
        float4 t4 = *(const float4*)(wvec + lane * 4 + j * 128);
        q[j*4+0] = t4.x; q[j*4+1] = t4.y; q[j*4+2] = t4.z; q[j*4+3] = t4.w;
    }

    float m = -INFINITY, s = 0.0f;
    float acc[16];
    #pragma unroll
    for (int k = 0; k < 16; k++) acc[k] = 0.0f;

    // prefetch t = w
    float v[16];
    {
        const float* p = base + (size_t)w * tstride;
        #pragma unroll
        for (int j = 0; j < 4; j++) {
            float4 t4 = *(const float4*)(p + j * 128);
            v[j*4+0] = t4.x; v[j*4+1] = t4.y; v[j*4+2] = t4.z; v[j*4+3] = t4.w;
        }
    }

    for (int i = 0; i < 25; i++) {
        int t = w + 8 * i;
        float vn[16];
        if (i < 24) {
            const float* p = base + (size_t)(t + 8) * tstride;
            #pragma unroll
            for (int j = 0; j < 4; j++) {
                float4 t4 = *(const float4*)(p + j * 128);
                vn[j*4+0] = t4.x; vn[j*4+1] = t4.y; vn[j*4+2] = t4.z; vn[j*4+3] = t4.w;
            }
        }
        float dot = 0.0f;
        #pragma unroll
        for (int k = 0; k < 16; k++) dot = fmaf(v[k], q[k], dot);
        #pragma unroll
        for (int o = 16; o > 0; o >>= 1) dot += __shfl_xor_sync(0xffffffffu, dot, o);

        if (WRITE_SCALE && lane == 0) scale_out[t * Bn + b] = dot;

        float nm = fmaxf(m, dot);
        float rs = __expf(m - nm);
        float cf = __expf(dot - nm);
        #pragma unroll
        for (int k = 0; k < 16; k++) acc[k] = fmaf(acc[k], rs, cf * v[k]);
        s = fmaf(s, rs, cf);
        m = nm;
        if (i < 24) {
            #pragma unroll
            for (int k = 0; k < 16; k++) v[k] = vn[k];
        }
    }

    // merge 8 warps
    if (lane == 0) { s_m[w] = m; s_s[w] = s; }
    #pragma unroll
    for (int j = 0; j < 4; j++)
        #pragma unroll
        for (int u = 0; u < 4; u++)
            s_acc[w][lane * 4 + j * 128 + u] = acc[j*4+u];
    __syncthreads();

    if (tid == 0) {
        float M = -INFINITY;
        #pragma unroll
        for (int k = 0; k < 8; k++) M = fmaxf(M, s_m[k]);
        float S = 0.0f;
        #pragma unroll
        for (int k = 0; k < 8; k++) S += s_s[k] * __expf(s_m[k] - M);
        float invS = 1.0f / S;
        #pragma unroll
        for (int k = 0; k < 8; k++) s_w8[k] = __expf(s_m[k] - M) * invS;
        if (m_out) { m_out[b] = M; s_out[b] = S; }
    }
    __syncthreads();

    int c = tid * 2;
    float o0 = 0.0f, o1 = 0.0f;
    #pragma unroll
    for (int k = 0; k < 8; k++) {
        float wk = s_w8[k];
        o0 = fmaf(s_acc[k][c], wk, o0);
        o1 = fmaf(s_acc[k][c + 1], wk, o1);
    }
    *(float2*)(c_out + c) = make_float2(o0, o1);
}

__global__ __launch_bounds__(256) void attn_g_kernel(
    const float* __restrict__ g_hist, const float* __restrict__ w_att,
    float* __restrict__ scale_out, float* __restrict__ m_out, float* __restrict__ s_out,
    float* __restrict__ c_out)
{
    int b = blockIdx.x;
    attn_body<1>(g_hist, (size_t)Bn * D_G, (size_t)b * D_G,
                 w_att, scale_out, b, m_out, s_out, c_out + (size_t)b * D_G);
}

__global__ __launch_bounds__(256) void attn_q_kernel(
    const float* __restrict__ q_hist, const float* __restrict__ xt,
    float* __restrict__ Qout)
{
    int n = blockIdx.x;
    attn_body<0>(q_hist, (size_t)Bn * PARTY * D_P, (size_t)n * D_P,
                 xt + (size_t)n * D_P, nullptr, n, nullptr, nullptr,
                 Qout + (size_t)n * D_P);
}

// alpha_out[b, 0, t] = exp(scale[t,b] - M[b]) / S[b]
__global__ void alpha_kernel(const float* __restrict__ scale_in,
                             const float* __restrict__ m_in, const float* __restrict__ s_in,
                             float* __restrict__ aout)
{
    int i = blockIdx.x * blockDim.x + threadIdx.x;
    if (i >= Tn * Bn) return;
    int t = i / Bn;
    int b = i - t * Bn;
    aout[b * Tn + t] = __expf(scale_in[i] - m_in[b]) / s_in[b];
}

// =====================================================================
// Batched SGEMM: C[n,m] = A[n,k]*W[m,k]^T + bias[m]
// 128x128 tile, TK=8, 256 threads, 8x8 microtile, packed f32x2 FMA.
// Descriptors passed by value in kernel params; block -> desc by range.
// =====================================================================
#define MAXD 5
struct GDesc {
    const float* A; const float* W; const float* bias; float* C;
    int K; int M; int gridX; int start;
};
struct GBatch { GDesc d[MAXD]; int nd; };

__global__ __launch_bounds__(256) void sgemm_batch(GBatch gb)
{
    __shared__ float As[2][8][128];
    __shared__ float Ws[2][8][128];

    int bid = blockIdx.x;
    int di = 0;
    #pragma unroll
    for (int k = 1; k < MAXD; k++)
        if (k < gb.nd && bid >= gb.d[k].start) di = k;
    const GDesc dd = gb.d[di];
    int local = bid - dd.start;
    int m0 = (local % dd.gridX) * 128;
    int n0 = (local / dd.gridX) * 128;
    int K = dd.K, M = dd.M;

    int tid = threadIdx.x;
    int lrow = tid >> 1;
    int lk = (tid & 1) * 4;
    int tx = tid & 15;
    int ty = tid >> 4;

    const float* Ap = dd.A + (size_t)(n0 + lrow) * K + lk;
    const float* Wp = dd.W + (size_t)(m0 + lrow) * K + lk;

    unsigned long long acc[8][4];
    #pragma unroll
    for (int i = 0; i < 8; i++)
        #pragma unroll
        for (int j = 0; j < 4; j++) acc[i][j] = 0ull;

    float4 a4 = *(const float4*)Ap;
    float4 w4 = *(const float4*)Wp;
    int buf = 0;
    for (int k0 = 0; k0 < K; k0 += 8) {
        As[buf][lk + 0][lrow] = a4.x; As[buf][lk + 1][lrow] = a4.y;
        As[buf][lk + 2][lrow] = a4.z; As[buf][lk + 3][lrow] = a4.w;
        Ws[buf][lk + 0][lrow] = w4.x; Ws[buf][lk + 1][lrow] = w4.y;
        Ws[buf][lk + 2][lrow] = w4.z; Ws[buf][lk + 3][lrow] = w4.w;
        __syncthreads();
        if (k0 + 8 < K) {
            a4 = *(const float4*)(Ap + k0 + 8);
            w4 = *(const float4*)(Wp + k0 + 8);
        }
        #pragma unroll
        for (int k = 0; k < 8; k++) {
            float4 av0 = *(const float4*)&As[buf][k][ty * 8];
            float4 av1 = *(const float4*)&As[buf][k][ty * 8 + 4];
            const unsigned long long* wp2 = (const unsigned long long*)&Ws[buf][k][tx * 8];
            unsigned long long w2[4];
            w2[0] = wp2[0]; w2[1] = wp2[1]; w2[2] = wp2[2]; w2[3] = wp2[3];
            float ar[8] = {av0.x, av0.y, av0.z, av0.w, av1.x, av1.y, av1.z, av1.w};
            #pragma unroll
            for (int i = 0; i < 8; i++) {
                unsigned int ai = __float_as_uint(ar[i]);
                unsigned long long a2;
                asm("mov.b64 %0, {%1, %1};" : "=l"(a2) : "r"(ai));
                #pragma unroll
                for (int j = 0; j < 4; j++) {
                    asm("fma.rn.f32x2 %0, %1, %2, %0;"
                        : "+l"(acc[i][j]) : "l"(a2), "l"(w2[j]));
                }
            }
        }
        buf ^= 1;
    }

    #pragma unroll
    for (int i = 0; i < 8; i++) {
        int row = n0 + ty * 8 + i;
        float* cp = dd.C + (size_t)row * M + m0 + tx * 8;
        #pragma unroll
        for (int j = 0; j < 4; j++) {
            unsigned int lo_u, hi_u;
            asm("mov.b64 {%0, %1}, %2;" : "=r"(lo_u), "=r"(hi_u) : "l"(acc[i][j]));
            float lo = __uint_as_float(lo_u);
            float hi = __uint_as_float(hi_u);
            int col = m0 + tx * 8 + 2 * j;
            if (dd.bias) { lo += dd.bias[col]; hi += dd.bias[col + 1]; }
            *(float2*)(cp + 2 * j) = make_float2(lo, hi);
        }
    }
}

// ---------------- GRU gating epilogue ----------------
// mode 0: plain. mode 1: party mix with deduped gi (gi row = n>>1)
__global__ void gru_epi(const float* __restrict__ gi, const float* __restrict__ gh,
                        const float* __restrict__ h, float* __restrict__ out,
                        int N, int D, int mode, const float* __restrict__ qmask)
{
    int idx = blockIdx.x * blockDim.x + threadIdx.x;
    if (idx >= N * D) return;
    int n = idx / D;
    int j = idx - n * D;
    int gn = (mode == 1) ? (n >> 1) : n;
    size_t gib = (size_t)gn * 3 * D + j;
    size_t ghb = (size_t)n * 3 * D + j;
    float ir = gi[gib],          hr = gh[ghb];
    float iz = gi[gib + D],      hz = gh[ghb + D];
    float in_ = gi[gib + 2 * D], hn = gh[ghb + 2 * D];
    float r = 1.0f / (1.0f + __expf(-(ir + hr)));
    float z = 1.0f / (1.0f + __expf(-(iz + hz)));
    float nn = tanhf(in_ + r * hn);
    float hv = h[idx];
    float val = (1.0f - z) * nn + z * hv;
    if (mode == 1) {
        float qm = qmask[n];
        val = hv * (1.0f - qm) + val * qm;
    }
    out[idx] = val;
}

// ---------------- small builders ----------------
__global__ void build_xcat_g(const float* __restrict__ U, const float* __restrict__ qmask,
                             const float* __restrict__ q0, float* __restrict__ xcat)
{
    int idx = blockIdx.x * blockDim.x + threadIdx.x;
    const int W = D_M + D_P;
    if (idx >= Bn * W) return;
    int b = idx / W;
    int c = idx - b * W;
    float v;
    if (c < D_M) {
        v = U[(size_t)b * D_M + c];
    } else {
        int qi = (qmask[b * 2 + 1] > qmask[b * 2 + 0]) ? 1 : 0;
        v = q0[(size_t)(b * 2 + qi) * D_P + (c - D_M)];
    }
    xcat[idx] = v;
}

// deduped xcat_p: only N=512 rows (one per b)
__global__ void build_xcat_p(const float* __restrict__ U, const float* __restrict__ c_,
                             float* __restrict__ xcat)
{
    int idx = blockIdx.x * blockDim.x + threadIdx.x;
    const int W = D_M + D_G;
    if (idx >= Bn * W) return;
    int b = idx / W;
    int c = idx - b * W;
    float v;
    if (c < D_M) v = U[(size_t)b * D_M + c];
    else         v = c_[(size_t)b * D_G + (c - D_M)];
    xcat[idx] = v;
}

__global__ void build_e0sw(const float* __restrict__ e0, float* __restrict__ e0sw)
{
    int idx = blockIdx.x * blockDim.x + threadIdx.x;
    if (idx >= Bn * PARTY * D_E) return;
    int n = idx / D_E;
    int j = idx - n * D_E;
    int b = n >> 1;
    int p = n & 1;
    e0sw[idx] = e0[(size_t)(b * 2 + (1 - p)) * D_E + j];
}

// ---------------- launch ----------------
extern "C" void kernel_launch(void* const* d_in, const int* in_sizes, int n_in,
                              void* d_out, int out_size)
{
    const float* U       = (const float*)d_in[0];
    const float* qmask   = (const float*)d_in[1];
    const float* g_hist  = (const float*)d_in[2];
    const float* q0      = (const float*)d_in[3];
    const float* q_hist  = (const float*)d_in[4];
    const float* e0      = (const float*)d_in[5];
    const float* w_ih_g  = (const float*)d_in[6];
    const float* w_hh_g  = (const float*)d_in[7];
    const float* b_ih_g  = (const float*)d_in[8];
    const float* b_hh_g  = (const float*)d_in[9];
    const float* w_ih_p  = (const float*)d_in[10];
    const float* w_hh_p  = (const float*)d_in[11];
    const float* b_ih_p  = (const float*)d_in[12];
    const float* b_hh_p  = (const float*)d_in[13];
    const float* w_ih_e  = (const float*)d_in[14];
    const float* w_hh_e  = (const float*)d_in[15];
    const float* b_ih_e  = (const float*)d_in[16];
    const float* b_hh_e  = (const float*)d_in[17];
    const float* w_att   = (const float*)d_in[18];
    const float* w_trans = (const float*)d_in[19];
    float* out = (float*)d_out;

    float *scale_p, *m_p, *s_p, *xcat_p, *gi_p, *gh_p, *ghp_p, *xt_p, *Q_p, *e0sw_p, *gih_p;
    cudaGetSymbolAddress((void**)&scale_p, d_scale_buf);
    cudaGetSymbolAddress((void**)&m_p,     d_m_buf);
    cudaGetSymbolAddress((void**)&s_p,     d_s_buf);
    cudaGetSymbolAddress((void**)&xcat_p,  d_xcat_buf);
    cudaGetSymbolAddress((void**)&gi_p,    d_gi_buf);
    cudaGetSymbolAddress((void**)&gh_p,    d_gh_buf);
    cudaGetSymbolAddress((void**)&ghp_p,   d_ghp_buf);
    cudaGetSymbolAddress((void**)&xt_p,    d_xt_buf);
    cudaGetSymbolAddress((void**)&Q_p,     d_Qacc_buf);
    cudaGetSymbolAddress((void**)&e0sw_p,  d_e0sw_buf);
    cudaGetSymbolAddress((void**)&gih_p,   d_gih_buf);

    const float* g_last = g_hist + (size_t)(Tn - 1) * Bn * D_G;

    // independent builders
    build_xcat_g<<<(Bn * (D_M + D_P) + 255) / 256, 256>>>(U, qmask, q0, xcat_p);
    build_e0sw<<<(Bn * PARTY * D_E + 255) / 256, 256>>>(e0, e0sw_p);

    // g-attention (c_, scale logits, M/S) + alpha output
    attn_g_kernel<<<Bn, 256>>>(g_hist, w_att, scale_p, m_p, s_p, out + C_OFF);
    alpha_kernel<<<(Tn * Bn + 255) / 256, 256>>>(scale_p, m_p, s_p, out + A_OFF);

    // xcat_p (needs c_); place after g-input region inside d_xcat_buf (2x sized)
    float* xcg = xcat_p;                         // [512, 1536]
    float* xcp = xcat_p + Bn * (D_M + D_P);      // [512, 1536]
    build_xcat_p<<<(Bn * (D_M + D_G) + 255) / 256, 256>>>(U, out + C_OFF, xcp);

    // Batch A: gi_g, gi_p (K=1536 first), gh_g, gh_p, xt
    {
        GBatch gb; gb.nd = 5;
        int s = 0;
        // gi_g: [512,1536] x [1536,1536]^T
        gb.d[0] = { xcg, w_ih_g, b_ih_g, gi_p, D_M + D_P, 3 * D_G, (3 * D_G) / 128, s };
        s += ((3 * D_G) / 128) * (Bn / 128);
        // gi_p dedup: [512,1536] x [1536,1536]^T
        gb.d[1] = { xcp, w_ih_p, b_ih_p, gih_p, D_M + D_G, 3 * D_P, (3 * D_P) / 128, s };
        s += ((3 * D_P) / 128) * (Bn / 128);
        // gh_g: [512,512] x [1536,512]^T
        gb.d[2] = { g_last, w_hh_g, b_hh_g, gh_p, D_G, 3 * D_G, (3 * D_G) / 128, s };
        s += ((3 * D_G) / 128) * (Bn / 128);
        // gh_p: [1024,512] x [1536,512]^T -> dedicated buffer (full 1024 rows)
        gb.d[3] = { q0, w_hh_p, b_hh_p, ghp_p, D_P, 3 * D_P, (3 * D_P) / 128, s };
        s += ((3 * D_P) / 128) * ((Bn * PARTY) / 128);
        // xt: [1024,512] x [512,512]^T
        gb.d[4] = { e0sw_p, w_trans, nullptr, xt_p, D_E, D_P, D_P / 128, s };
        s += (D_P / 128) * ((Bn * PARTY) / 128);
        sgemm_batch<<<s, 256>>>(gb);
    }

    // epilogues for g and p
    gru_epi<<<(Bn * D_G + 255) / 256, 256>>>(gi_p, gh_p, g_last, out + G_OFF, Bn, D_G, 0, nullptr);
    gru_epi<<<(Bn * PARTY * D_P + 255) / 256, 256>>>(gih_p, ghp_p, q0, out + Q_OFF,
                                                     Bn * PARTY, D_P, 1, qmask);

    // q-attention (needs xt)
    attn_q_kernel<<<Bn * PARTY, 256>>>(q_hist, xt_p, Q_p);

    // Batch B: gi_e, gh_e
    {
        GBatch gb; gb.nd = 2;
        int s = 0;
        gb.d[0] = { Q_p, w_ih_e, b_ih_e, gi_p, D_P, 3 * D_E, (3 * D_E) / 128, s };
        s += ((3 * D_E) / 128) * ((Bn * PARTY) / 128);
        gb.d[1] = { e0, w_hh_e, b_hh_e, gh_p, D_E, 3 * D_E, (3 * D_E) / 128, s };
        s += ((3 * D_E) / 128) * ((Bn * PARTY) / 128);
        gb.d[2] = gb.d[0]; gb.d[3] = gb.d[0]; gb.d[4] = gb.d[0];  // pad (unused)
        sgemm_batch<<<s, 256>>>(gb);
    }

    gru_epi<<<(Bn * PARTY * D_E + 255) / 256, 256>>>(gi_p, gh_p, e0, out + E_OFF,
                                                     Bn * PARTY, D_E, 0, nullptr);
}

// round 5
// speedup vs baseline: 2.2430x; 1.2137x over previous
#include <cuda_runtime.h>
#include <math.h>

#define Bn 512
#define Tn 200
#define PARTY 2
#define D_M 1024
#define D_G 512
#define D_P 512
#define D_E 512

// Output layout (flattened tuple): g_, q_, e_, c_, alpha_out
#define G_OFF 0
#define Q_OFF (Bn * D_G)                    // 262144
#define E_OFF (Q_OFF + Bn * PARTY * D_P)    // 786432
#define C_OFF (E_OFF + Bn * PARTY * D_E)    // 1310720
#define A_OFF (C_OFF + Bn * D_G)            // 1572864

// ---------------- static scratch (no allocations allowed) ----------------
__device__ float d_scale_buf[Tn * Bn];
__device__ float d_m_buf[Bn];
__device__ float d_s_buf[Bn];
__device__ float d_xcat_buf[(Bn * PARTY) * (D_M + D_G)];
__device__ float d_gi_buf[(Bn * PARTY) * 3 * D_G];   // L1: gi_g h1|h2 ; L5: gi_e (full)
__device__ float d_gh_buf[(Bn * PARTY) * 3 * D_G];   // L1: gh_g ; L5: gh_e (full)
__device__ float d_ghp_buf[(Bn * PARTY) * 3 * D_P];  // gh_p (1024 rows)
__device__ float d_xt_buf[Bn * PARTY * D_P];
__device__ float d_Qacc_buf[Bn * PARTY * D_P];
__device__ float d_e0sw_buf[Bn * PARTY * D_E];
__device__ float d_gih_buf[Bn * 3 * D_P];    // gi_p dedup, K-half 1
__device__ float d_gih2_buf[Bn * 3 * D_P];   // gi_p dedup, K-half 2

// shared memory: union of gemm (16384B) and attn (16480B) layouts
#define SMEM_BYTES 16512
struct AttnSmem {
    float m[8]; float s[8]; float w8[8];
    float acc[8][512];
};

// =====================================================================
// Attention body: per-warp online softmax, no per-timestep block syncs.
// Block = one row. 8 warps; warp w owns t = w + 8*i.
// =====================================================================
template<int WRITE_SCALE>
__device__ __forceinline__ void attn_body(
    char* smem_raw,
    const float* __restrict__ hist, size_t tstride, size_t row_off,
    const float* __restrict__ wvec,
    float* __restrict__ scale_out, int b,
    float* __restrict__ m_out, float* __restrict__ s_out,
    float* __restrict__ c_out)
{
    AttnSmem* sm = reinterpret_cast<AttnSmem*>(smem_raw);
    int tid = threadIdx.x;
    int lane = tid & 31;
    int w = tid >> 5;

    const float* base = hist + row_off + (size_t)lane * 4;
    float q[16];
    #pragma unroll
    for (int j = 0; j < 4; j++) {
        float4 t4 = *(const float4*)(wvec + lane * 4 + j * 128);
        q[j*4+0] = t4.x; q[j*4+1] = t4.y; q[j*4+2] = t4.z; q[j*4+3] = t4.w;
    }

    float m = -INFINITY, s = 0.0f;
    float acc[16];
    #pragma unroll
    for (int k = 0; k < 16; k++) acc[k] = 0.0f;

    float v[16];
    {
        const float* p = base + (size_t)w * tstride;
        #pragma unroll
        for (int j = 0; j < 4; j++) {
            float4 t4 = *(const float4*)(p + j * 128);
            v[j*4+0] = t4.x; v[j*4+1] = t4.y; v[j*4+2] = t4.z; v[j*4+3] = t4.w;
        }
    }

    for (int i = 0; i < 25; i++) {
        int t = w + 8 * i;
        float vn[16];
        if (i < 24) {
            const float* p = base + (size_t)(t + 8) * tstride;
            #pragma unroll
            for (int j = 0; j < 4; j++) {
                float4 t4 = *(const float4*)(p + j * 128);
                vn[j*4+0] = t4.x; vn[j*4+1] = t4.y; vn[j*4+2] = t4.z; vn[j*4+3] = t4.w;
            }
        }
        float dot = 0.0f;
        #pragma unroll
        for (int k = 0; k < 16; k++) dot = fmaf(v[k], q[k], dot);
        #pragma unroll
        for (int o = 16; o > 0; o >>= 1) dot += __shfl_xor_sync(0xffffffffu, dot, o);

        if (WRITE_SCALE && lane == 0) scale_out[t * Bn + b] = dot;

        float nm = fmaxf(m, dot);
        float rs = __expf(m - nm);
        float cf = __expf(dot - nm);
        #pragma unroll
        for (int k = 0; k < 16; k++) acc[k] = fmaf(acc[k], rs, cf * v[k]);
        s = fmaf(s, rs, cf);
        m = nm;
        if (i < 24) {
            #pragma unroll
            for (int k = 0; k < 16; k++) v[k] = vn[k];
        }
    }

    if (lane == 0) { sm->m[w] = m; sm->s[w] = s; }
    #pragma unroll
    for (int j = 0; j < 4; j++)
        #pragma unroll
        for (int u = 0; u < 4; u++)
            sm->acc[w][lane * 4 + j * 128 + u] = acc[j*4+u];
    __syncthreads();

    if (tid == 0) {
        float M = -INFINITY;
        #pragma unroll
        for (int k = 0; k < 8; k++) M = fmaxf(M, sm->m[k]);
        float S = 0.0f;
        #pragma unroll
        for (int k = 0; k < 8; k++) S += sm->s[k] * __expf(sm->m[k] - M);
        float invS = 1.0f / S;
        #pragma unroll
        for (int k = 0; k < 8; k++) sm->w8[k] = __expf(sm->m[k] - M) * invS;
        if (m_out) { m_out[b] = M; s_out[b] = S; }
    }
    __syncthreads();

    int c = tid * 2;
    float o0 = 0.0f, o1 = 0.0f;
    #pragma unroll
    for (int k = 0; k < 8; k++) {
        float wk = sm->w8[k];
        o0 = fmaf(sm->acc[k][c], wk, o0);
        o1 = fmaf(sm->acc[k][c + 1], wk, o1);
    }
    *(float2*)(c_out + c) = make_float2(o0, o1);
}

// =====================================================================
// GEMM body: C[n,m] = A[n,k]*W[m,k]^T + bias[m]   (lda = row stride of A/W)
// 128x128 tile, TK=8, 256 threads, 8x8 microtile, packed f32x2 FMA.
// =====================================================================
#define MAXD 5
struct GDesc {
    const float* A; const float* W; const float* bias; float* C;
    int lda; int K; int M; int gridX; int start;
};
struct GBatch { GDesc d[MAXD]; int nd; };

__device__ __forceinline__ void gemm_body(const GBatch& gb, char* smem_raw)
{
    float (*As)[8][128] = reinterpret_cast<float(*)[8][128]>(smem_raw);
    float (*Ws)[8][128] = reinterpret_cast<float(*)[8][128]>(smem_raw + 8192);

    int bid = blockIdx.x;
    int di = 0;
    #pragma unroll
    for (int k = 1; k < MAXD; k++)
        if (k < gb.nd && bid >= gb.d[k].start) di = k;
    const GDesc dd = gb.d[di];
    int local = bid - dd.start;
    int m0 = (local % dd.gridX) * 128;
    int n0 = (local / dd.gridX) * 128;
    int K = dd.K, M = dd.M, lda = dd.lda;

    int tid = threadIdx.x;
    int lrow = tid >> 1;
    int lk = (tid & 1) * 4;
    int tx = tid & 15;
    int ty = tid >> 4;

    const float* Ap = dd.A + (size_t)(n0 + lrow) * lda + lk;
    const float* Wp = dd.W + (size_t)(m0 + lrow) * lda + lk;

    unsigned long long acc[8][4];
    #pragma unroll
    for (int i = 0; i < 8; i++)
        #pragma unroll
        for (int j = 0; j < 4; j++) acc[i][j] = 0ull;

    float4 a4 = *(const float4*)Ap;
    float4 w4 = *(const float4*)Wp;
    int buf = 0;
    for (int k0 = 0; k0 < K; k0 += 8) {
        As[buf][lk + 0][lrow] = a4.x; As[buf][lk + 1][lrow] = a4.y;
        As[buf][lk + 2][lrow] = a4.z; As[buf][lk + 3][lrow] = a4.w;
        Ws[buf][lk + 0][lrow] = w4.x; Ws[buf][lk + 1][lrow] = w4.y;
        Ws[buf][lk + 2][lrow] = w4.z; Ws[buf][lk + 3][lrow] = w4.w;
        __syncthreads();
        if (k0 + 8 < K) {
            a4 = *(const float4*)(Ap + k0 + 8);
            w4 = *(const float4*)(Wp + k0 + 8);
        }
        #pragma unroll
        for (int k = 0; k < 8; k++) {
            float4 av0 = *(const float4*)&As[buf][k][ty * 8];
            float4 av1 = *(const float4*)&As[buf][k][ty * 8 + 4];
            const unsigned long long* wp2 = (const unsigned long long*)&Ws[buf][k][tx * 8];
            unsigned long long w2[4];
            w2[0] = wp2[0]; w2[1] = wp2[1]; w2[2] = wp2[2]; w2[3] = wp2[3];
            float ar[8] = {av0.x, av0.y, av0.z, av0.w, av1.x, av1.y, av1.z, av1.w};
            #pragma unroll
            for (int i = 0; i < 8; i++) {
                unsigned int ai = __float_as_uint(ar[i]);
                unsigned long long a2;
                asm("mov.b64 %0, {%1, %1};" : "=l"(a2) : "r"(ai));
                #pragma unroll
                for (int j = 0; j < 4; j++) {
                    asm("fma.rn.f32x2 %0, %1, %2, %0;"
                        : "+l"(acc[i][j]) : "l"(a2), "l"(w2[j]));
                }
            }
        }
        buf ^= 1;
    }

    #pragma unroll
    for (int i = 0; i < 8; i++) {
        int row = n0 + ty * 8 + i;
        float* cp = dd.C + (size_t)row * M + m0 + tx * 8;
        #pragma unroll
        for (int j = 0; j < 4; j++) {
            unsigned int lo_u, hi_u;
            asm("mov.b64 {%0, %1}, %2;" : "=r"(lo_u), "=r"(hi_u) : "l"(acc[i][j]));
            float lo = __uint_as_float(lo_u);
            float hi = __uint_as_float(hi_u);
            int col = m0 + tx * 8 + 2 * j;
            if (dd.bias) { lo += dd.bias[col]; hi += dd.bias[col + 1]; }
            *(float2*)(cp + 2 * j) = make_float2(lo, hi);
        }
    }
}

// =====================================================================
// Fused heterogeneous launches
// =====================================================================
__global__ __launch_bounds__(256, 2) void fused_gemm_attn_g(
    GBatch gb, int n_gemm,
    const float* __restrict__ g_hist, const float* __restrict__ w_att,
    float* __restrict__ scale_out, float* __restrict__ m_out, float* __restrict__ s_out,
    float* __restrict__ c_out)
{
    __shared__ __align__(16) char smem_raw[SMEM_BYTES];
    if ((int)blockIdx.x < n_gemm) {
        gemm_body(gb, smem_raw);
    } else {
        int b = blockIdx.x - n_gemm;
        attn_body<1>(smem_raw, g_hist, (size_t)Bn * D_G, (size_t)b * D_G,
                     w_att, scale_out, b, m_out, s_out, c_out + (size_t)b * D_G);
    }
}

__global__ __launch_bounds__(256, 2) void fused_gemm_attn_q(
    GBatch gb, int n_gemm,
    const float* __restrict__ q_hist, const float* __restrict__ xt,
    float* __restrict__ Qout)
{
    __shared__ __align__(16) char smem_raw[SMEM_BYTES];
    if ((int)blockIdx.x < n_gemm) {
        gemm_body(gb, smem_raw);
    } else {
        int n = blockIdx.x - n_gemm;
        attn_body<0>(smem_raw, q_hist, (size_t)Bn * PARTY * D_P, (size_t)n * D_P,
                     xt + (size_t)n * D_P, nullptr, n, nullptr, nullptr,
                     Qout + (size_t)n * D_P);
    }
}

// alpha_out[b, 0, t] = exp(scale[t,b] - M[b]) / S[b]
__global__ void alpha_kernel(const float* __restrict__ scale_in,
                             const float* __restrict__ m_in, const float* __restrict__ s_in,
                             float* __restrict__ aout)
{
    int i = blockIdx.x * blockDim.x + threadIdx.x;
    if (i >= Tn * Bn) return;
    int t = i / Bn;
    int b = i - t * Bn;
    aout[b * Tn + t] = __expf(scale_in[i] - m_in[b]) / s_in[b];
}

// ---------------- GRU gating epilogue (with optional K-split addend) -----
// mode 0: plain. mode 1: party mix with deduped gi (gi row = n>>1)
__global__ void gru_epi(const float* __restrict__ gi, const float* __restrict__ gi2,
                        const float* __restrict__ gh,
                        const float* __restrict__ h, float* __restrict__ out,
                        int N, int D, int mode, const float* __restrict__ qmask)
{
    int idx = blockIdx.x * blockDim.x + threadIdx.x;
    if (idx >= N * D) return;
    int n = idx / D;
    int j = idx - n * D;
    int gn = (mode == 1) ? (n >> 1) : n;
    size_t gib = (size_t)gn * 3 * D + j;
    size_t ghb = (size_t)n * 3 * D + j;
    float ir = gi[gib],          hr = gh[ghb];
    float iz = gi[gib + D],      hz = gh[ghb + D];
    float in_ = gi[gib + 2 * D], hn = gh[ghb + 2 * D];
    if (gi2) {
        ir += gi2[gib]; iz += gi2[gib + D]; in_ += gi2[gib + 2 * D];
    }
    float r = 1.0f / (1.0f + __expf(-(ir + hr)));
    float z = 1.0f / (1.0f + __expf(-(iz + hz)));
    float nn = tanhf(in_ + r * hn);
    float hv = h[idx];
    float val = (1.0f - z) * nn + z * hv;
    if (mode == 1) {
        float qm = qmask[n];
        val = hv * (1.0f - qm) + val * qm;
    }
    out[idx] = val;
}

// ---------------- small builders ----------------
__global__ void build_xcat_g(const float* __restrict__ U, const float* __restrict__ qmask,
                             const float* __restrict__ q0, float* __restrict__ xcat)
{
    int idx = blockIdx.x * blockDim.x + threadIdx.x;
    const int W = D_M + D_P;
    if (idx >= Bn * W) return;
    int b = idx / W;
    int c = idx - b * W;
    float v;
    if (c < D_M) {
        v = U[(size_t)b * D_M + c];
    } else {
        int qi = (qmask[b * 2 + 1] > qmask[b * 2 + 0]) ? 1 : 0;
        v = q0[(size_t)(b * 2 + qi) * D_P + (c - D_M)];
    }
    xcat[idx] = v;
}

__global__ void build_xcat_p(const float* __restrict__ U, const float* __restrict__ c_,
                             float* __restrict__ xcat)
{
    int idx = blockIdx.x * blockDim.x + threadIdx.x;
    const int W = D_M + D_G;
    if (idx >= Bn * W) return;
    int b = idx / W;
    int c = idx - b * W;
    float v;
    if (c < D_M) v = U[(size_t)b * D_M + c];
    else         v = c_[(size_t)b * D_G + (c - D_M)];
    xcat[idx] = v;
}

__global__ void build_e0sw(const float* __restrict__ e0, float* __restrict__ e0sw)
{
    int idx = blockIdx.x * blockDim.x + threadIdx.x;
    if (idx >= Bn * PARTY * D_E) return;
    int n = idx / D_E;
    int j = idx - n * D_E;
    int b = n >> 1;
    int p = n & 1;
    e0sw[idx] = e0[(size_t)(b * 2 + (1 - p)) * D_E + j];
}

// ---------------- launch ----------------
extern "C" void kernel_launch(void* const* d_in, const int* in_sizes, int n_in,
                              void* d_out, int out_size)
{
    const float* U       = (const float*)d_in[0];
    const float* qmask   = (const float*)d_in[1];
    const float* g_hist  = (const float*)d_in[2];
    const float* q0      = (const float*)d_in[3];
    const float* q_hist  = (const float*)d_in[4];
    const float* e0      = (const float*)d_in[5];
    const float* w_ih_g  = (const float*)d_in[6];
    const float* w_hh_g  = (const float*)d_in[7];
    const float* b_ih_g  = (const float*)d_in[8];
    const float* b_hh_g  = (const float*)d_in[9];
    const float* w_ih_p  = (const float*)d_in[10];
    const float* w_hh_p  = (const float*)d_in[11];
    const float* b_ih_p  = (const float*)d_in[12];
    const float* b_hh_p  = (const float*)d_in[13];
    const float* w_ih_e  = (const float*)d_in[14];
    const float* w_hh_e  = (const float*)d_in[15];
    const float* b_ih_e  = (const float*)d_in[16];
    const float* b_hh_e  = (const float*)d_in[17];
    const float* w_att   = (const float*)d_in[18];
    const float* w_trans = (const float*)d_in[19];
    float* out = (float*)d_out;

    float *scale_p, *m_p, *s_p, *xcat_p, *gi_p, *gh_p, *ghp_p, *xt_p, *Q_p, *e0sw_p, *gih_p, *gih2_p;
    cudaGetSymbolAddress((void**)&scale_p, d_scale_buf);
    cudaGetSymbolAddress((void**)&m_p,     d_m_buf);
    cudaGetSymbolAddress((void**)&s_p,     d_s_buf);
    cudaGetSymbolAddress((void**)&xcat_p,  d_xcat_buf);
    cudaGetSymbolAddress((void**)&gi_p,    d_gi_buf);
    cudaGetSymbolAddress((void**)&gh_p,    d_gh_buf);
    cudaGetSymbolAddress((void**)&ghp_p,   d_ghp_buf);
    cudaGetSymbolAddress((void**)&xt_p,    d_xt_buf);
    cudaGetSymbolAddress((void**)&Q_p,     d_Qacc_buf);
    cudaGetSymbolAddress((void**)&e0sw_p,  d_e0sw_buf);
    cudaGetSymbolAddress((void**)&gih_p,   d_gih_buf);
    cudaGetSymbolAddress((void**)&gih2_p,  d_gih2_buf);

    const float* g_last = g_hist + (size_t)(Tn - 1) * Bn * D_G;
    float* xcg = xcat_p;                         // [512, 1536]
    float* xcp = xcat_p + Bn * (D_M + D_P);      // [512, 1536]
    float* gi1 = gi_p;                           // gi_g K-half 1 [512,1536]
    float* gi2 = gi_p + Bn * 3 * D_G;            // gi_g K-half 2 [512,1536]

    // L0: independent builders
    build_xcat_g<<<(Bn * (D_M + D_P) + 255) / 256, 256>>>(U, qmask, q0, xcat_p);
    build_e0sw<<<(Bn * PARTY * D_E + 255) / 256, 256>>>(e0, e0sw_p);

    // L1: fused {gi_g(2 K-halves), gh_g, gh_p, xt} + attn_g
    {
        GBatch gb; gb.nd = 5;
        int s = 0;
        gb.d[0] = { xcg,       w_ih_g,       b_ih_g, gi1,   D_M + D_P, 768, 3 * D_G, (3 * D_G) / 128, s };
        s += 48;
        gb.d[1] = { xcg + 768, w_ih_g + 768, nullptr, gi2,  D_M + D_P, 768, 3 * D_G, (3 * D_G) / 128, s };
        s += 48;
        gb.d[2] = { g_last, w_hh_g, b_hh_g, gh_p,  D_G, D_G, 3 * D_G, (3 * D_G) / 128, s };
        s += 48;
        gb.d[3] = { q0,     w_hh_p, b_hh_p, ghp_p, D_P, D_P, 3 * D_P, (3 * D_P) / 128, s };
        s += 96;
        gb.d[4] = { e0sw_p, w_trans, nullptr, xt_p, D_E, D_E, D_P, D_P / 128, s };
        s += 32;
        fused_gemm_attn_g<<<s + Bn, 256>>>(gb, s, g_hist, w_att,
                                           scale_p, m_p, s_p, out + C_OFF);
    }

    // L2: alpha output + xcat_p (needs c_)
    alpha_kernel<<<(Tn * Bn + 255) / 256, 256>>>(scale_p, m_p, s_p, out + A_OFF);
    build_xcat_p<<<(Bn * (D_M + D_G) + 255) / 256, 256>>>(U, out + C_OFF, xcp);

    // L3: fused gi_p (2 K-halves, dedup N=512) + attn_q
    {
        GBatch gb; gb.nd = 2;
        int s = 0;
        gb.d[0] = { xcp,       w_ih_p,       b_ih_p, gih_p,  D_M + D_G, 768, 3 * D_P, (3 * D_P) / 128, s };
        s += 48;
        gb.d[1] = { xcp + 768, w_ih_p + 768, nullptr, gih2_p, D_M + D_G, 768, 3 * D_P, (3 * D_P) / 128, s };
        s += 48;
        gb.d[2] = gb.d[0]; gb.d[3] = gb.d[0]; gb.d[4] = gb.d[0];
        fused_gemm_attn_q<<<s + Bn * PARTY, 256>>>(gb, s, q_hist, xt_p, Q_p);
    }

    // L4: epilogues g and p
    gru_epi<<<(Bn * D_G + 255) / 256, 256>>>(gi1, gi2, gh_p, g_last, out + G_OFF,
                                             Bn, D_G, 0, nullptr);
    gru_epi<<<(Bn * PARTY * D_P + 255) / 256, 256>>>(gih_p, gih2_p, ghp_p, q0, out + Q_OFF,
                                                     Bn * PARTY, D_P, 1, qmask);

    // L5: gi_e + gh_e (reuse fused kernel, no attn blocks)
    {
        GBatch gb; gb.nd = 2;
        int s = 0;
        gb.d[0] = { Q_p, w_ih_e, b_ih_e, gi_p, D_P, D_P, 3 * D_E, (3 * D_E) / 128, s };
        s += 96;
        gb.d[1] = { e0,  w_hh_e, b_hh_e, gh_p, D_E, D_E, 3 * D_E, (3 * D_E) / 128, s };
        s += 96;
        gb.d[2] = gb.d[0]; gb.d[3] = gb.d[0]; gb.d[4] = gb.d[0];
        fused_gemm_attn_q<<<s, 256>>>(gb, s, q_hist, xt_p, Q_p);
    }

    // L6: epilogue e
    gru_epi<<<(Bn * PARTY * D_E + 255) / 256, 256>>>(gi_p, nullptr, gh_p, e0, out + E_OFF,
                                                     Bn * PARTY, D_E, 0, nullptr);
}

// round 7
// speedup vs baseline: 3.4144x; 1.5222x over previous
#include <cuda_runtime.h>
#include <cuda_bf16.h>
#include <math.h>
#include <stdint.h>

#define Bn 512
#define Tn 200
#define PARTY 2
#define D_M 1024
#define D_G 512
#define D_P 512
#define D_E 512

// Output layout (flattened tuple): g_, q_, e_, c_, alpha_out
#define G_OFF 0
#define Q_OFF (Bn * D_G)
#define E_OFF (Q_OFF + Bn * PARTY * D_P)
#define C_OFF (E_OFF + Bn * PARTY * D_E)
#define A_OFF (C_OFF + Bn * D_G)

// ---------------- fp32 scratch ----------------
__device__ float d_scale_buf[Tn * Bn];
__device__ float d_m_buf[Bn];
__device__ float d_s_buf[Bn];
__device__ float d_xcat_buf[(Bn * PARTY) * (D_M + D_G)];
__device__ float d_gi_buf[(Bn * PARTY) * 3 * D_G];
__device__ float d_gh_buf[(Bn * PARTY) * 3 * D_G];
__device__ float d_ghp_buf[(Bn * PARTY) * 3 * D_P];
__device__ float d_xt_buf[Bn * PARTY * D_P];
__device__ float d_Qacc_buf[Bn * PARTY * D_P];
__device__ float d_e0sw_buf[Bn * PARTY * D_E];
__device__ float d_gih_buf[Bn * 3 * D_P];

// ---------------- bf16 split scratch (hi/lo concat, K tripled) ----------------
#define OFF_WIHG  0ull                       // 1536 x 4608
#define OFF_WHHG  (OFF_WIHG  + 7077888ull)   // 1536 x 1536
#define OFF_WIHP  (OFF_WHHG  + 2359296ull)   // 1536 x 4608
#define OFF_WHHP  (OFF_WIHP  + 7077888ull)   // 1536 x 1536
#define OFF_WIHE  (OFF_WHHP  + 2359296ull)   // 1536 x 1536
#define OFF_WHHE  (OFF_WIHE  + 2359296ull)   // 1536 x 1536
#define OFF_WTR   (OFF_WHHE  + 2359296ull)   // 512 x 1536
#define OFF_XCG   (OFF_WTR   + 786432ull)    // 512 x 4608
#define OFF_GLAST (OFF_XCG   + 2359296ull)   // 512 x 1536
#define OFF_Q0    (OFF_GLAST + 786432ull)    // 1024 x 1536
#define OFF_E0SW  (OFF_Q0    + 1572864ull)   // 1024 x 1536
#define OFF_E0    (OFF_E0SW  + 1572864ull)   // 1024 x 1536
#define OFF_XCP   (OFF_E0    + 1572864ull)   // 512 x 4608
#define OFF_QC    (OFF_XCP   + 2359296ull)   // 1024 x 1536
#define BF_TOTAL  (OFF_QC    + 1572864ull)
__device__ __align__(16) __nv_bfloat16 d_bf[BF_TOTAL];

// =====================================================================
// helpers
// =====================================================================
__device__ __forceinline__ uint32_t smem_u32(const void* p) {
    uint32_t r;
    asm("{ .reg .u64 t; cvta.to.shared.u64 t, %1; cvt.u32.u64 %0, t; }" : "=r"(r) : "l"(p));
    return r;
}

__device__ __forceinline__ void cp_async16(uint32_t dst, const void* src) {
    asm volatile("cp.async.cg.shared.global [%0], [%1], 16;" :: "r"(dst), "l"(src) : "memory");
}
__device__ __forceinline__ void cp_commit() {
    asm volatile("cp.async.commit_group;" ::: "memory");
}
template<int N>
__device__ __forceinline__ void cp_wait() {
    asm volatile("cp.async.wait_group %0;" :: "n"(N) : "memory");
}

__device__ __forceinline__ void ldmatrix_x4(uint32_t& r0, uint32_t& r1, uint32_t& r2, uint32_t& r3,
                                            uint32_t addr) {
    asm volatile("ldmatrix.sync.aligned.m8n8.x4.shared.b16 {%0,%1,%2,%3}, [%4];"
                 : "=r"(r0), "=r"(r1), "=r"(r2), "=r"(r3) : "r"(addr));
}

__device__ __forceinline__ void mma_bf16(float* d, const uint32_t* a, const uint32_t* b) {
    asm volatile("mma.sync.aligned.m16n8k16.row.col.f32.bf16.bf16.f32 "
                 "{%0,%1,%2,%3}, {%4,%5,%6,%7}, {%8,%9}, {%0,%1,%2,%3};"
                 : "+f"(d[0]), "+f"(d[1]), "+f"(d[2]), "+f"(d[3])
                 : "r"(a[0]), "r"(a[1]), "r"(a[2]), "r"(a[3]), "r"(b[0]), "r"(b[1]));
}

// =====================================================================
// Attention body (R5-proven): per-warp online softmax
// =====================================================================
struct AttnSmem {
    float m[8]; float s[8]; float w8[8];
    float acc[8][512];
};

template<int WRITE_SCALE>
__device__ __forceinline__ void attn_body(
    char* smem_raw,
    const float* __restrict__ hist, size_t tstride, size_t row_off,
    const float* __restrict__ wvec,
    float* __restrict__ scale_out, int b,
    float* __restrict__ m_out, float* __restrict__ s_out,
    float* __restrict__ c_out)
{
    AttnSmem* sm = reinterpret_cast<AttnSmem*>(smem_raw);
    int tid = threadIdx.x;
    int lane = tid & 31;
    int w = tid >> 5;

    const float* base = hist + row_off + (size_t)lane * 4;
    float q[16];
    #pragma unroll
    for (int j = 0; j < 4; j++) {
        float4 t4 = *(const float4*)(wvec + lane * 4 + j * 128);
        q[j*4+0] = t4.x; q[j*4+1] = t4.y; q[j*4+2] = t4.z; q[j*4+3] = t4.w;
    }

    float m = -INFINITY, s = 0.0f;
    float acc[16];
    #pragma unroll
    for (int k = 0; k < 16; k++) acc[k] = 0.0f;

    float v[16];
    {
        const float* p = base + (size_t)w * tstride;
        #pragma unroll
        for (int j = 0; j < 4; j++) {
            float4 t4 = *(const float4*)(p + j * 128);
            v[j*4+0] = t4.x; v[j*4+1] = t4.y; v[j*4+2] = t4.z; v[j*4+3] = t4.w;
        }
    }

    for (int i = 0; i < 25; i++) {
        int t = w + 8 * i;
        float vn[16];
        if (i < 24) {
            const float* p = base + (size_t)(t + 8) * tstride;
            #pragma unroll
            for (int j = 0; j < 4; j++) {
                float4 t4 = *(const float4*)(p + j * 128);
                vn[j*4+0] = t4.x; vn[j*4+1] = t4.y; vn[j*4+2] = t4.z; vn[j*4+3] = t4.w;
            }
        }
        float dot = 0.0f;
        #pragma unroll
        for (int k = 0; k < 16; k++) dot = fmaf(v[k], q[k], dot);
        #pragma unroll
        for (int o = 16; o > 0; o >>= 1) dot += __shfl_xor_sync(0xffffffffu, dot, o);

        if (WRITE_SCALE && lane == 0) scale_out[t * Bn + b] = dot;

        float nm = fmaxf(m, dot);
        float rs = __expf(m - nm);
        float cf = __expf(dot - nm);
        #pragma unroll
        for (int k = 0; k < 16; k++) acc[k] = fmaf(acc[k], rs, cf * v[k]);
        s = fmaf(s, rs, cf);
        m = nm;
        if (i < 24) {
            #pragma unroll
            for (int k = 0; k < 16; k++) v[k] = vn[k];
        }
    }

    if (lane == 0) { sm->m[w] = m; sm->s[w] = s; }
    #pragma unroll
    for (int j = 0; j < 4; j++)
        #pragma unroll
        for (int u = 0; u < 4; u++)
            sm->acc[w][lane * 4 + j * 128 + u] = acc[j*4+u];
    __syncthreads();

    if (tid == 0) {
        float M = -INFINITY;
        #pragma unroll
        for (int k = 0; k < 8; k++) M = fmaxf(M, sm->m[k]);
        float S = 0.0f;
        #pragma unroll
        for (int k = 0; k < 8; k++) S += sm->s[k] * __expf(sm->m[k] - M);
        float invS = 1.0f / S;
        #pragma unroll
        for (int k = 0; k < 8; k++) sm->w8[k] = __expf(sm->m[k] - M) * invS;
        if (m_out) { m_out[b] = M; s_out[b] = S; }
    }
    __syncthreads();

    int c = tid * 2;
    float o0 = 0.0f, o1 = 0.0f;
    #pragma unroll
    for (int k = 0; k < 8; k++) {
        float wk = sm->w8[k];
        o0 = fmaf(sm->acc[k][c], wk, o0);
        o1 = fmaf(sm->acc[k][c + 1], wk, o1);
    }
    *(float2*)(c_out + c) = make_float2(o0, o1);
}

// =====================================================================
// bf16 mma.sync GEMM body: C[n,m] = A[n,k]·W[m,k]^T + bias[m]
// 128x128 tile, 8 warps (2x4), warp tile 64x32 via m16n8k16.
// K chunks of 64 bf16 (128B swizzled rows), cp.async double buffer.
// =====================================================================
#define MAXT 4
struct TDesc {
    const __nv_bfloat16* A; const __nv_bfloat16* W;
    const float* bias; float* C;
    int K3; int M; int gridX; int start;
};
struct TBatch { TDesc d[MAXT]; int nd; };

// dynamic smem: 2 buffers x (A 16K + B 16K) = 64 KB (attn uses first ~16.5K)
#define DYN_SMEM_BYTES 65536

__device__ __forceinline__ void mma_gemm_body(const TBatch& tb, char* smem_raw)
{
    int tid = threadIdx.x;
    int wid = tid >> 5;
    int lane = tid & 31;

    int bid = blockIdx.x;
    int di = 0;
    #pragma unroll
    for (int k = 1; k < MAXT; k++)
        if (k < tb.nd && bid >= tb.d[k].start) di = k;
    const TDesc dd = tb.d[di];
    int local = bid - dd.start;
    int m0 = (local % dd.gridX) * 128;
    int n0 = (local / dd.gridX) * 128;
    const int K3 = dd.K3;
    const int nc = K3 >> 6;

    uint32_t sb = smem_u32(smem_raw);

    // loader mapping: 1024 16B-units per tile; unit u -> row=u>>3, c16=u&7
    int lrow[4]; uint32_t swoff[4];
    #pragma unroll
    for (int i = 0; i < 4; i++) {
        int u = tid + 256 * i;
        int r = u >> 3, c16 = u & 7;
        lrow[i] = r;
        swoff[i] = (uint32_t)(r * 128 + 16 * (c16 ^ (r & 7)));
    }
    const __nv_bfloat16* Ab = dd.A + (size_t)n0 * K3;
    const __nv_bfloat16* Wb = dd.W + (size_t)m0 * K3;

    // mma lane constants
    int xr = lane & 7;
    int lA_row = (lane & 7) + ((lane >> 3) & 1) * 8;
    int lA_kh = lane >> 4;
    int lB_row = (lane & 7) + (lane >> 4) * 8;
    int lB_kh = (lane >> 3) & 1;
    int wr = wid & 1;     // row block (64)
    int wc = wid >> 1;    // col block (32)
    uint32_t rbA[4], rbB[2];
    #pragma unroll
    for (int mt = 0; mt < 4; mt++) rbA[mt] = (uint32_t)((wr * 64 + mt * 16 + lA_row) * 128);
    #pragma unroll
    for (int p = 0; p < 2; p++) rbB[p] = (uint32_t)((wc * 32 + p * 16 + lB_row) * 128);

    float acc[4][4][4];
    #pragma unroll
    for (int mt = 0; mt < 4; mt++)
        #pragma unroll
        for (int nt = 0; nt < 4; nt++)
            #pragma unroll
            for (int r = 0; r < 4; r++) acc[mt][nt][r] = 0.0f;

    // issue chunk c into buffer buf
    auto issue = [&](int c, int buf) {
        uint32_t ba = sb + (uint32_t)buf * 32768u;
        uint32_t bb = ba + 16384u;
        int koff = c * 64;
        #pragma unroll
        for (int i = 0; i < 4; i++) {
            const __nv_bfloat16* sa = Ab + (size_t)lrow[i] * K3 + koff + (swoff[i] == 0 ? 0 : 0);
            // src col from unit index: c16 = original; recompute from swoff is wrong — use stored
            (void)sa;
        }
        // (real loads below — need original c16, keep separate array)
        (void)ba; (void)bb;
    };
    (void)issue;

    // re-derive c16 per unit (kept separate from swizzled offset)
    int lc16[4];
    #pragma unroll
    for (int i = 0; i < 4; i++) lc16[i] = (tid + 256 * i) & 7;

    // prologue: chunk 0 -> buf 0
    {
        uint32_t ba = sb, bb = sb + 16384u;
        #pragma unroll
        for (int i = 0; i < 4; i++) {
            cp_async16(ba + swoff[i], Ab + (size_t)lrow[i] * K3 + lc16[i] * 8);
            cp_async16(bb + swoff[i], Wb + (size_t)lrow[i] * K3 + lc16[i] * 8);
        }
        cp_commit();
    }

    for (int c = 0; c < nc; c++) {
        if (c + 1 < nc) {
            uint32_t ba = sb + (uint32_t)((c + 1) & 1) * 32768u;
            uint32_t bb = ba + 16384u;
            int koff = (c + 1) * 64;
            #pragma unroll
            for (int i = 0; i < 4; i++) {
                cp_async16(ba + swoff[i], Ab + (size_t)lrow[i] * K3 + koff + lc16[i] * 8);
                cp_async16(bb + swoff[i], Wb + (size_t)lrow[i] * K3 + koff + lc16[i] * 8);
            }
            cp_commit();
            cp_wait<1>();
        } else {
            cp_wait<0>();
        }
        __syncthreads();

        uint32_t ba = sb + (uint32_t)(c & 1) * 32768u;
        uint32_t bb = ba + 16384u;
        #pragma unroll
        for (int s = 0; s < 4; s++) {
            uint32_t a[4][4];
            #pragma unroll
            for (int mt = 0; mt < 4; mt++) {
                uint32_t addr = ba + rbA[mt] + 16u * (uint32_t)(((s << 1) + lA_kh) ^ xr);
                ldmatrix_x4(a[mt][0], a[mt][1], a[mt][2], a[mt][3], addr);
            }
            uint32_t bfr[4][2];
            #pragma unroll
            for (int p = 0; p < 2; p++) {
                uint32_t addr = bb + rbB[p] + 16u * (uint32_t)(((s << 1) + lB_kh) ^ xr);
                ldmatrix_x4(bfr[2*p][0], bfr[2*p][1], bfr[2*p+1][0], bfr[2*p+1][1], addr);
            }
            #pragma unroll
            for (int mt = 0; mt < 4; mt++)
                #pragma unroll
                for (int nt = 0; nt < 4; nt++)
                    mma_bf16(acc[mt][nt], a[mt], bfr[nt]);
        }
        __syncthreads();
    }

    // epilogue: write C from register fragments
    int g = lane >> 2;
    int t2 = (lane & 3) * 2;
    #pragma unroll
    for (int mt = 0; mt < 4; mt++) {
        int row0 = n0 + wr * 64 + mt * 16 + g;
        #pragma unroll
        for (int nt = 0; nt < 4; nt++) {
            int col = m0 + wc * 32 + nt * 8 + t2;
            float b0 = 0.0f, b1 = 0.0f;
            if (dd.bias) { b0 = dd.bias[col]; b1 = dd.bias[col + 1]; }
            float2 v0 = make_float2(acc[mt][nt][0] + b0, acc[mt][nt][1] + b1);
            float2 v1 = make_float2(acc[mt][nt][2] + b0, acc[mt][nt][3] + b1);
            *(float2*)(dd.C + (size_t)row0 * dd.M + col) = v0;
            *(float2*)(dd.C + (size_t)(row0 + 8) * dd.M + col) = v1;
        }
    }
}

// =====================================================================
// Fused heterogeneous launches (dynamic smem)
// =====================================================================
__global__ __launch_bounds__(256, 2) void fused_mma_attn_g(
    TBatch tb, int n_gemm,
    const float* __restrict__ g_hist, const float* __restrict__ w_att,
    float* __restrict__ scale_out, float* __restrict__ m_out, float* __restrict__ s_out,
    float* __restrict__ c_out)
{
    extern __shared__ __align__(128) char smem_raw[];
    if ((int)blockIdx.x < n_gemm) {
        mma_gemm_body(tb, smem_raw);
    } else {
        int b = blockIdx.x - n_gemm;
        attn_body<1>(smem_raw, g_hist, (size_t)Bn * D_G, (size_t)b * D_G,
                     w_att, scale_out, b, m_out, s_out, c_out + (size_t)b * D_G);
    }
}

__global__ __launch_bounds__(256, 2) void fused_mma_attn_q(
    TBatch tb, int n_gemm,
    const float* __restrict__ q_hist, const float* __restrict__ xt,
    float* __restrict__ Qout)
{
    extern __shared__ __align__(128) char smem_raw[];
    if ((int)blockIdx.x < n_gemm) {
        mma_gemm_body(tb, smem_raw);
    } else {
        int n = blockIdx.x - n_gemm;
        attn_body<0>(smem_raw, q_hist, (size_t)Bn * PARTY * D_P, (size_t)n * D_P,
                     xt + (size_t)n * D_P, nullptr, n, nullptr, nullptr,
                     Qout + (size_t)n * D_P);
    }
}

// =====================================================================
// fp32 -> bf16 hi/lo split conversion, batched.
// mode 0 (activation): [hi | lo | hi]; mode 1 (weight): [hi | hi | lo]
// =====================================================================
#define MAXC 12
struct CDesc { const float* in; __nv_bfloat16* out; int K; int total; int start; int mode; };
struct CBatch { CDesc d[MAXC]; int nd; };

__global__ __launch_bounds__(256) void conv_batch(CBatch cb)
{
    int bid = blockIdx.x;
    int di = 0;
    #pragma unroll
    for (int k = 1; k < MAXC; k++)
        if (k < cb.nd && bid >= cb.d[k].start) di = k;
    const CDesc dd = cb.d[di];
    int base = (bid - dd.start) * 2048 + threadIdx.x;
    #pragma unroll
    for (int i = 0; i < 8; i++) {
        int idx = base + i * 256;
        if (idx >= dd.total) break;
        int r = idx / dd.K;
        int k = idx - r * dd.K;
        float x = dd.in[idx];
        __nv_bfloat16 hi = __float2bfloat16(x);
        __nv_bfloat16 lo = __float2bfloat16(x - __bfloat162float(hi));
        __nv_bfloat16* o = dd.out + (size_t)r * 3 * dd.K + k;
        if (dd.mode == 0) { o[0] = hi; o[dd.K] = lo; o[2 * dd.K] = hi; }
        else              { o[0] = hi; o[dd.K] = hi; o[2 * dd.K] = lo; }
    }
}

// =====================================================================
// alpha / GRU epilogue / builders
// =====================================================================
__global__ void alpha_kernel(const float* __restrict__ scale_in,
                             const float* __restrict__ m_in, const float* __restrict__ s_in,
                             float* __restrict__ aout)
{
    int i = blockIdx.x * blockDim.x + threadIdx.x;
    if (i >= Tn * Bn) return;
    int t = i / Bn;
    int b = i - t * Bn;
    aout[b * Tn + t] = __expf(scale_in[i] - m_in[b]) / s_in[b];
}

__global__ void gru_epi(const float* __restrict__ gi, const float* __restrict__ gh,
                        const float* __restrict__ h, float* __restrict__ out,
                        int N, int D, int mode, const float* __restrict__ qmask)
{
    int idx = blockIdx.x * blockDim.x + threadIdx.x;
    if (idx >= N * D) return;
    int n = idx / D;
    int j = idx - n * D;
    int gn = (mode == 1) ? (n >> 1) : n;
    size_t gib = (size_t)gn * 3 * D + j;
    size_t ghb = (size_t)n * 3 * D + j;
    float ir = gi[gib],          hr = gh[ghb];
    float iz = gi[gib + D],      hz = gh[ghb + D];
    float in_ = gi[gib + 2 * D], hn = gh[ghb + 2 * D];
    float r = 1.0f / (1.0f + __expf(-(ir + hr)));
    float z = 1.0f / (1.0f + __expf(-(iz + hz)));
    float nn = tanhf(in_ + r * hn);
    float hv = h[idx];
    float val = (1.0f - z) * nn + z * hv;
    if (mode == 1) {
        float qm = qmask[n];
        val = hv * (1.0f - qm) + val * qm;
    }
    out[idx] = val;
}

__global__ void build_xcat_g(const float* __restrict__ U, const float* __restrict__ qmask,
                             const float* __restrict__ q0, float* __restrict__ xcat)
{
    int idx = blockIdx.x * blockDim.x + threadIdx.x;
    const int W = D_M + D_P;
    if (idx >= Bn * W) return;
    int b = idx / W;
    int c = idx - b * W;
    float v;
    if (c < D_M) {
        v = U[(size_t)b * D_M + c];
    } else {
        int qi = (qmask[b * 2 + 1] > qmask[b * 2 + 0]) ? 1 : 0;
        v = q0[(size_t)(b * 2 + qi) * D_P + (c - D_M)];
    }
    xcat[idx] = v;
}

__global__ void build_xcat_p(const float* __restrict__ U, const float* __restrict__ c_,
                             float* __restrict__ xcat)
{
    int idx = blockIdx.x * blockDim.x + threadIdx.x;
    const int W = D_M + D_G;
    if (idx >= Bn * W) return;
    int b = idx / W;
    int c = idx - b * W;
    float v;
    if (c < D_M) v = U[(size_t)b * D_M + c];
    else         v = c_[(size_t)b * D_G + (c - D_M)];
    xcat[idx] = v;
}

__global__ void build_e0sw(const float* __restrict__ e0, float* __restrict__ e0sw)
{
    int idx = blockIdx.x * blockDim.x + threadIdx.x;
    if (idx >= Bn * PARTY * D_E) return;
    int n = idx / D_E;
    int j = idx - n * D_E;
    int b = n >> 1;
    int p = n & 1;
    e0sw[idx] = e0[(size_t)(b * 2 + (1 - p)) * D_E + j];
}

// =====================================================================
// launch
// =====================================================================
extern "C" void kernel_launch(void* const* d_in, const int* in_sizes, int n_in,
                              void* d_out, int out_size)
{
    const float* U       = (const float*)d_in[0];
    const float* qmask   = (const float*)d_in[1];
    const float* g_hist  = (const float*)d_in[2];
    const float* q0      = (const float*)d_in[3];
    const float* q_hist  = (const float*)d_in[4];
    const float* e0      = (const float*)d_in[5];
    const float* w_ih_g  = (const float*)d_in[6];
    const float* w_hh_g  = (const float*)d_in[7];
    const float* b_ih_g  = (const float*)d_in[8];
    const float* b_hh_g  = (const float*)d_in[9];
    const float* w_ih_p  = (const float*)d_in[10];
    const float* w_hh_p  = (const float*)d_in[11];
    const float* b_ih_p  = (const float*)d_in[12];
    const float* b_hh_p  = (const float*)d_in[13];
    const float* w_ih_e  = (const float*)d_in[14];
    const float* w_hh_e  = (const float*)d_in[15];
    const float* b_ih_e  = (const float*)d_in[16];
    const float* b_hh_e  = (const float*)d_in[17];
    const float* w_att   = (const float*)d_in[18];
    const float* w_trans = (const float*)d_in[19];
    float* out = (float*)d_out;

    static int smem_set = 0;
    if (!smem_set) {
        cudaFuncSetAttribute(fused_mma_attn_g, cudaFuncAttributeMaxDynamicSharedMemorySize, DYN_SMEM_BYTES);
        cudaFuncSetAttribute(fused_mma_attn_q, cudaFuncAttributeMaxDynamicSharedMemorySize, DYN_SMEM_BYTES);
        smem_set = 1;
    }

    float *scale_p, *m_p, *s_p, *xcat_p, *gi_p, *gh_p, *ghp_p, *xt_p, *Q_p, *e0sw_p, *gih_p;
    __nv_bfloat16* bf;
    cudaGetSymbolAddress((void**)&scale_p, d_scale_buf);
    cudaGetSymbolAddress((void**)&m_p,     d_m_buf);
    cudaGetSymbolAddress((void**)&s_p,     d_s_buf);
    cudaGetSymbolAddress((void**)&xcat_p,  d_xcat_buf);
    cudaGetSymbolAddress((void**)&gi_p,    d_gi_buf);
    cudaGetSymbolAddress((void**)&gh_p,    d_gh_buf);
    cudaGetSymbolAddress((void**)&ghp_p,   d_ghp_buf);
    cudaGetSymbolAddress((void**)&xt_p,    d_xt_buf);
    cudaGetSymbolAddress((void**)&Q_p,     d_Qacc_buf);
    cudaGetSymbolAddress((void**)&e0sw_p,  d_e0sw_buf);
    cudaGetSymbolAddress((void**)&gih_p,   d_gih_buf);
    cudaGetSymbolAddress((void**)&bf,      d_bf);

    const float* g_last = g_hist + (size_t)(Tn - 1) * Bn * D_G;
    float* xcg = xcat_p;
    float* xcp = xcat_p + Bn * (D_M + D_P);

    // L0: builders + all independent conversions
    build_xcat_g<<<(Bn * (D_M + D_P) + 255) / 256, 256>>>(U, qmask, q0, xcg);
    build_e0sw<<<(Bn * PARTY * D_E + 255) / 256, 256>>>(e0, e0sw_p);
    {
        CBatch cb; cb.nd = 12;
        int s = 0;
        auto add = [&](int i, const float* in, unsigned long long off, int K, int total, int mode) {
            cb.d[i] = { in, bf + off, K, total, s, mode };
            s += total / 2048;
        };
        add(0,  w_ih_g,  OFF_WIHG,  1536, 1536 * 1536, 1);
        add(1,  w_hh_g,  OFF_WHHG,  512,  1536 * 512,  1);
        add(2,  w_ih_p,  OFF_WIHP,  1536, 1536 * 1536, 1);
        add(3,  w_hh_p,  OFF_WHHP,  512,  1536 * 512,  1);
        add(4,  w_ih_e,  OFF_WIHE,  512,  1536 * 512,  1);
        add(5,  w_hh_e,  OFF_WHHE,  512,  1536 * 512,  1);
        add(6,  w_trans, OFF_WTR,   512,  512 * 512,   1);
        add(7,  xcg,     OFF_XCG,   1536, 512 * 1536,  0);
        add(8,  g_last,  OFF_GLAST, 512,  512 * 512,   0);
        add(9,  q0,      OFF_Q0,    512,  1024 * 512,  0);
        add(10, e0sw_p,  OFF_E0SW,  512,  1024 * 512,  0);
        add(11, e0,      OFF_E0,    512,  1024 * 512,  0);
        conv_batch<<<s, 256>>>(cb);
    }

    // L1: mma {gi_g, gh_g, gh_p, xt} + attn_g
    {
        TBatch tb; tb.nd = 4;
        int s = 0;
        tb.d[0] = { bf + OFF_XCG,   bf + OFF_WIHG, b_ih_g, gi_p,  4608, 3 * D_G, 12, s }; s += 48;
        tb.d[1] = { bf + OFF_GLAST, bf + OFF_WHHG, b_hh_g, gh_p,  1536, 3 * D_G, 12, s }; s += 48;
        tb.d[2] = { bf + OFF_Q0,    bf + OFF_WHHP, b_hh_p, ghp_p, 1536, 3 * D_P, 12, s }; s += 96;
        tb.d[3] = { bf + OFF_E0SW,  bf + OFF_WTR,  nullptr, xt_p, 1536, D_P,      4, s }; s += 32;
        fused_mma_attn_g<<<s + Bn, 256, DYN_SMEM_BYTES>>>(tb, s, g_hist, w_att,
                                                          scale_p, m_p, s_p, out + C_OFF);
    }

    // L2: alpha, xcat_p build + conversion
    alpha_kernel<<<(Tn * Bn + 255) / 256, 256>>>(scale_p, m_p, s_p, out + A_OFF);
    build_xcat_p<<<(Bn * (D_M + D_G) + 255) / 256, 256>>>(U, out + C_OFF, xcp);
    {
        CBatch cb; cb.nd = 1;
        cb.d[0] = { xcp, bf + OFF_XCP, 1536, 512 * 1536, 0, 0 };
        conv_batch<<<(512 * 1536) / 2048, 256>>>(cb);
    }

    // L3: mma {gi_p dedup} + attn_q
    {
        TBatch tb; tb.nd = 1;
        tb.d[0] = { bf + OFF_XCP, bf + OFF_WIHP, b_ih_p, gih_p, 4608, 3 * D_P, 12, 0 };
        int s = 48;
        fused_mma_attn_q<<<s + Bn * PARTY, 256, DYN_SMEM_BYTES>>>(tb, s, q_hist, xt_p, Q_p);
    }

    // L4: epilogues g,p + Q conversion
    gru_epi<<<(Bn * D_G + 255) / 256, 256>>>(gi_p, gh_p, g_last, out + G_OFF, Bn, D_G, 0, nullptr);
    gru_epi<<<(Bn * PARTY * D_P + 255) / 256, 256>>>(gih_p, ghp_p, q0, out + Q_OFF,
                                                     Bn * PARTY, D_P, 1, qmask);
    {
        CBatch cb; cb.nd = 1;
        cb.d[0] = { Q_p, bf + OFF_QC, 512, 1024 * 512, 0, 0 };
        conv_batch<<<(1024 * 512) / 2048, 256>>>(cb);
    }

    // L5: mma {gi_e, gh_e}
    {
        TBatch tb; tb.nd = 2;
        int s = 0;
        tb.d[0] = { bf + OFF_QC, bf + OFF_WIHE, b_ih_e, gi_p, 1536, 3 * D_E, 12, s }; s += 96;
        tb.d[1] = { bf + OFF_E0, bf + OFF_WHHE, b_hh_e, gh_p, 1536, 3 * D_E, 12, s }; s += 96;
        fused_mma_attn_q<<<s, 256, DYN_SMEM_BYTES>>>(tb, s, q_hist, xt_p, Q_p);
    }

    // L6: epilogue e
    gru_epi<<<(Bn * PARTY * D_E + 255) / 256, 256>>>(gi_p, gh_p, e0, out + E_OFF,
                                                     Bn * PARTY, D_E, 0, nullptr);
}